// round 5
// baseline (speedup 1.0000x reference)
#include <cuda_runtime.h>
#include <cstdint>

#define NMP     3
#define NNODES  50000
#define D       128
#define E       32
#define DEG     32
#define NEDGE   200000
#define BB      1024
#define S       16
#define NC      8
#define M1      (BB*S)      /* 16384 */
#define DE      (D+E)       /* 160 */

// ---------------- scratch (static device globals; no runtime alloc) ----------------
__device__ int   g_nb1 [NMP*M1];
__device__ int   g_eid1[NMP*M1];
__device__ float g_nin2[(size_t)NMP*M1*DE];
__device__ float g_nin1[NMP*BB*DE];
__device__ float g_h1  [(size_t)NMP*M1*D];
__device__ float g_h0  [NMP*BB*D];
__device__ float g_ninL1[NMP*BB*DE];
__device__ float g_outs[NMP*BB*D];
// merged + tf32-pre-rounded weights: g_Wh[wl][k=288][n=128] (k<128: W_self, k>=128: W_neigh)
__device__ float g_Wh[NMP*2*288*128];
__device__ float g_We[NMP*2*288*32];

// ---------------- helpers ----------------
__device__ __forceinline__ float tf32r(float x) {
    uint32_t u; asm("cvt.rna.tf32.f32 %0, %1;" : "=r"(u) : "f"(x));
    return __uint_as_float(u);
}
__device__ __forceinline__ uint32_t fu(float x) { return __float_as_uint(x); }

#define MMA_TF32(c, a, b) \
    asm volatile("mma.sync.aligned.m16n8k8.row.col.f32.tf32.tf32.f32 " \
        "{%0,%1,%2,%3}, {%4,%5,%6,%7}, {%8,%9}, {%0,%1,%2,%3};" \
        : "+f"((c)[0]), "+f"((c)[1]), "+f"((c)[2]), "+f"((c)[3]) \
        : "r"((a)[0]), "r"((a)[1]), "r"((a)[2]), "r"((a)[3]), \
          "r"((b)[0]), "r"((b)[1]))

// ---------------- 0) merge + pre-round weights to tf32 ----------------
__global__ void k_round_w(const float* __restrict__ W_self,
                          const float* __restrict__ W_neigh,
                          const float* __restrict__ W_edge) {
    int t = blockIdx.x * blockDim.x + threadIdx.x;
    if (t < NMP*2*288*128) {
        int wl = t / (288*128);
        int r  = t % (288*128);
        int k  = r / 128, n = r % 128;
        float v = (k < 128) ? W_self [wl*128*128 + k*128 + n]
                            : W_neigh[wl*160*128 + (k-128)*128 + n];
        g_Wh[t] = tf32r(v);
    }
    if (t < NMP*2*288*32) g_We[t] = tf32r(W_edge[t]);
}

// ---------------- 1) hop-1 neighbor / edge ids ----------------
__global__ void k_idx(const int* __restrict__ ids,
                      const int* __restrict__ adj_nodes,
                      const int* __restrict__ adj_edges) {
    int t = blockIdx.x * blockDim.x + threadIdx.x;
    if (t >= NMP * M1) return;
    int mp = t / M1;
    int r  = t % M1;
    int b  = r >> 4;
    int s  = r & 15;
    long base = ((long)mp * NNODES + ids[b]) * DEG + s;
    g_nb1[t]  = adj_nodes[base];
    g_eid1[t] = adj_edges[base];
}

// ---------------- 2) hop-2 gather + mean -> nin2 ----------------
__global__ void k_mean_hop2(const float* __restrict__ feats,
                            const float* __restrict__ edge_emb,
                            const int* __restrict__ adj_nodes,
                            const int* __restrict__ adj_edges) {
    int w    = (blockIdx.x * blockDim.x + threadIdx.x) >> 5;
    int lane = threadIdx.x & 31;
    if (w >= NMP * M1) return;
    int mp = w / M1;
    long abase = ((long)mp * NNODES + g_nb1[w]) * DEG;
    const int* an = adj_nodes + abase;
    const int* ae = adj_edges + abase;
    float4 aF = make_float4(0.f,0.f,0.f,0.f);
    float4 aE = make_float4(0.f,0.f,0.f,0.f);
    #pragma unroll
    for (int s = 0; s < S; s++) {
        int nb = an[s];
        float4 v = ((const float4*)(feats + (long)nb * D))[lane];
        aF.x += v.x; aF.y += v.y; aF.z += v.z; aF.w += v.w;
        if (lane < E/4) {
            int e = ae[s];
            float4 u = ((const float4*)(edge_emb + ((long)mp * NEDGE + e) * E))[lane];
            aE.x += u.x; aE.y += u.y; aE.z += u.z; aE.w += u.w;
        }
    }
    const float inv = 1.0f / S;
    float4* o = (float4*)(g_nin2 + (size_t)w * DE);
    o[lane] = make_float4(aF.x*inv, aF.y*inv, aF.z*inv, aF.w*inv);
    if (lane < E/4)
        o[D/4 + lane] = make_float4(aE.x*inv, aE.y*inv, aE.z*inv, aE.w*inv);
}

// ---------------- 3) hop-1 gather + mean -> nin1 ----------------
__global__ void k_mean_hop1(const float* __restrict__ feats,
                            const float* __restrict__ edge_emb) {
    int w    = (blockIdx.x * blockDim.x + threadIdx.x) >> 5;
    int lane = threadIdx.x & 31;
    if (w >= NMP * BB) return;
    int mp = w / BB;
    int b  = w % BB;
    int base = mp * M1 + b * S;
    float4 aF = make_float4(0.f,0.f,0.f,0.f);
    float4 aE = make_float4(0.f,0.f,0.f,0.f);
    #pragma unroll
    for (int s = 0; s < S; s++) {
        int nb = g_nb1[base + s];
        float4 v = ((const float4*)(feats + (long)nb * D))[lane];
        aF.x += v.x; aF.y += v.y; aF.z += v.z; aF.w += v.w;
        if (lane < E/4) {
            int e = g_eid1[base + s];
            float4 u = ((const float4*)(edge_emb + ((long)mp * NEDGE + e) * E))[lane];
            aE.x += u.x; aE.y += u.y; aE.z += u.z; aE.w += u.w;
        }
    }
    const float inv = 1.0f / S;
    float4* o = (float4*)(g_nin1 + (size_t)w * DE);
    o[lane] = make_float4(aF.x*inv, aF.y*inv, aF.z*inv, aF.w*inv);
    if (lane < E/4)
        o[D/4 + lane] = make_float4(aE.x*inv, aE.y*inv, aE.z*inv, aE.w*inv);
}

// ---------------- node GEMM: register-direct TF32 mma, NO smem staging ----------------
// out = relu([P1 || P2] @ Wh), K = 288; tile 64m x 128n per CTA (128 thr, 4 warps)
// MODE 0: h1 (M=16384) + fused 16-row mean -> g_ninL1[:, :D]
// MODE 1: h0 (M=1024)   MODE 2: outs (M=1024)
template<int MODE>
__global__ __launch_bounds__(128) void gemm_h(const float* __restrict__ feats,
                                              const int*   __restrict__ ids,
                                              int l) {
    constexpr int M = (MODE == 0) ? M1 : BB;
    int mp   = blockIdx.y;
    int m0   = blockIdx.x * 64;
    int tid  = threadIdx.x;
    int lane = tid & 31;
    int wn   = tid >> 5;        // warp -> n-slice (32 cols)
    int q    = lane >> 2;       // 0..7
    int c4   = lane & 3;        // 0..3

    // per-lane row pointers: j = 2*mt + hi -> row m0 + mt*16 + hi*8 + q
    const float* fpp[8];
    const float* npp[8];
    #pragma unroll
    for (int j = 0; j < 8; j++) {
        int m = m0 + (j >> 1) * 16 + (j & 1) * 8 + q;
        const float* p;
        if (MODE == 0)      p = feats + (size_t)g_nb1[mp * M1 + m] * D;
        else if (MODE == 1) p = feats + (size_t)ids[m] * D;
        else                p = g_h0 + ((size_t)mp * BB + m) * D;
        fpp[j] = p;
        const float* n2;
        if (MODE == 0)      n2 = g_nin2  + ((size_t)mp * M  + m) * DE;
        else if (MODE == 1) n2 = g_nin1  + ((size_t)mp * BB + m) * DE;
        else                n2 = g_ninL1 + ((size_t)mp * BB + m) * DE;
        npp[j] = n2 - 128;  // so ptr + k works for k >= 128
    }
    // B pointer: col = wn*32 + nt*8 + q, row k
    const float* Wp = g_Wh + (size_t)(mp * 2 + l) * 288 * 128 + wn * 32 + q;

    float acc[4][4][4];
    #pragma unroll
    for (int i = 0; i < 4; i++)
        #pragma unroll
        for (int j = 0; j < 4; j++)
            #pragma unroll
            for (int t = 0; t < 4; t++) acc[i][j][t] = 0.f;

    float    a[2][16];
    uint32_t bv[2][8];

#define LD_H(HS, BUF) do {                                                      \
    int _k = (HS) * 8 + c4;                                                     \
    _Pragma("unroll")                                                           \
    for (int j = 0; j < 8; j++) {                                               \
        const float* p = ((HS) < 16) ? fpp[j] : npp[j];                         \
        a[BUF][j*2+0] = tf32r(p[_k]);                                           \
        a[BUF][j*2+1] = tf32r(p[_k + 4]);                                       \
    }                                                                           \
    const float* wb = Wp + (size_t)_k * 128;                                    \
    _Pragma("unroll")                                                           \
    for (int nt = 0; nt < 4; nt++) {                                            \
        bv[BUF][nt*2+0] = fu(wb[nt*8]);                                         \
        bv[BUF][nt*2+1] = fu(wb[nt*8 + 4*128]);                                 \
    }                                                                           \
} while (0)

#define MMA_H(BUF) do {                                                         \
    _Pragma("unroll")                                                           \
    for (int mt = 0; mt < 4; mt++) {                                            \
        uint32_t af[4] = { fu(a[BUF][4*mt]),   fu(a[BUF][4*mt+2]),              \
                           fu(a[BUF][4*mt+1]), fu(a[BUF][4*mt+3]) };            \
        _Pragma("unroll")                                                       \
        for (int nt = 0; nt < 4; nt++)                                          \
            MMA_TF32(acc[mt][nt], af, &bv[BUF][2*nt]);                          \
    }                                                                           \
} while (0)

    LD_H(0, 0);
    #pragma unroll 3
    for (int h2 = 0; h2 < 18; h2++) {
        LD_H(2*h2 + 1, 1);
        MMA_H(0);
        if (h2 < 17) LD_H(2*h2 + 2, 0);
        MMA_H(1);
    }
#undef LD_H
#undef MMA_H

    #pragma unroll
    for (int mt = 0; mt < 4; mt++)
        #pragma unroll
        for (int nt = 0; nt < 4; nt++)
            #pragma unroll
            for (int t = 0; t < 4; t++)
                acc[mt][nt][t] = fmaxf(acc[mt][nt][t], 0.f);

    float* Out = (MODE == 0) ? g_h1 : (MODE == 1) ? g_h0 : g_outs;
    size_t ob = ((size_t)mp * M + m0) * D;
    #pragma unroll
    for (int mt = 0; mt < 4; mt++) {
        int r = mt * 16 + q;
        #pragma unroll
        for (int nt = 0; nt < 4; nt++) {
            int c = wn * 32 + nt * 8 + 2 * c4;
            *(float2*)(Out + ob + (size_t)r       * D + c) = make_float2(acc[mt][nt][0], acc[mt][nt][1]);
            *(float2*)(Out + ob + (size_t)(r + 8) * D + c) = make_float2(acc[mt][nt][2], acc[mt][nt][3]);
        }
    }

    if (MODE == 0) {
        const float inv16 = 1.0f / 16.0f;
        #pragma unroll
        for (int mt = 0; mt < 4; mt++) {
            int b = (m0 + mt * 16) >> 4;
            float* dst = g_ninL1 + ((size_t)mp * BB + b) * DE;
            #pragma unroll
            for (int nt = 0; nt < 4; nt++) {
                float s0 = acc[mt][nt][0] + acc[mt][nt][2];
                float s1 = acc[mt][nt][1] + acc[mt][nt][3];
                #pragma unroll
                for (int o = 4; o < 32; o <<= 1) {
                    s0 += __shfl_xor_sync(0xffffffffu, s0, o);
                    s1 += __shfl_xor_sync(0xffffffffu, s1, o);
                }
                if (lane < 4) {
                    int c = wn * 32 + nt * 8 + 2 * lane;
                    *(float2*)(dst + c) = make_float2(s0 * inv16, s1 * inv16);
                }
            }
        }
    }
}

// ---------------- edge GEMM: register-direct TF32, fused mean -> ninL1[:, D:] ----------------
// tile 128m x 32n per CTA (128 thr, 4 warps; warp = 32m x 32n)
__global__ __launch_bounds__(128) void gemm_edge(const float* __restrict__ edge_emb,
                                                 int l) {
    int mp   = blockIdx.y;
    int m0   = blockIdx.x * 128;
    int tid  = threadIdx.x;
    int lane = tid & 31;
    int w    = tid >> 5;
    int q    = lane >> 2;
    int c4   = lane & 3;

    const float* p0[4];
    const float* p1[4];
    const float* pe[4];
    #pragma unroll
    for (int j = 0; j < 4; j++) {
        int m = m0 + w * 32 + (j >> 1) * 16 + (j & 1) * 8 + q;
        p0[j] = g_h0 + ((size_t)mp * BB + (m >> 4)) * D;
        p1[j] = g_h1 + ((size_t)mp * M1 + m) * D - 128;
        pe[j] = edge_emb + ((size_t)mp * NEDGE + g_eid1[mp * M1 + m]) * E - 256;
    }
    const float* Wp = g_We + (size_t)(mp * 2 + l) * 288 * 32 + q;

    float acc[2][4][4];
    #pragma unroll
    for (int i = 0; i < 2; i++)
        #pragma unroll
        for (int j = 0; j < 4; j++)
            #pragma unroll
            for (int t = 0; t < 4; t++) acc[i][j][t] = 0.f;

    float    a[2][8];
    uint32_t bv[2][8];

#define LD_E(HS, BUF) do {                                                      \
    int _k = (HS) * 8 + c4;                                                     \
    _Pragma("unroll")                                                           \
    for (int j = 0; j < 4; j++) {                                               \
        const float* p = ((HS) < 16) ? p0[j] : (((HS) < 32) ? p1[j] : pe[j]);   \
        a[BUF][j*2+0] = tf32r(p[_k]);                                           \
        a[BUF][j*2+1] = tf32r(p[_k + 4]);                                       \
    }                                                                           \
    const float* wb = Wp + (size_t)_k * 32;                                     \
    _Pragma("unroll")                                                           \
    for (int nt = 0; nt < 4; nt++) {                                            \
        bv[BUF][nt*2+0] = fu(wb[nt*8]);                                         \
        bv[BUF][nt*2+1] = fu(wb[nt*8 + 4*32]);                                  \
    }                                                                           \
} while (0)

#define MMA_E(BUF) do {                                                         \
    _Pragma("unroll")                                                           \
    for (int mt = 0; mt < 2; mt++) {                                            \
        uint32_t af[4] = { fu(a[BUF][4*mt]),   fu(a[BUF][4*mt+2]),              \
                           fu(a[BUF][4*mt+1]), fu(a[BUF][4*mt+3]) };            \
        _Pragma("unroll")                                                       \
        for (int nt = 0; nt < 4; nt++)                                          \
            MMA_TF32(acc[mt][nt], af, &bv[BUF][2*nt]);                          \
    }                                                                           \
} while (0)

    LD_E(0, 0);
    #pragma unroll 3
    for (int h2 = 0; h2 < 18; h2++) {
        LD_E(2*h2 + 1, 1);
        MMA_E(0);
        if (h2 < 17) LD_E(2*h2 + 2, 0);
        MMA_E(1);
    }
#undef LD_E
#undef MMA_E

    const float inv16 = 1.0f / 16.0f;
    #pragma unroll
    for (int mt = 0; mt < 2; mt++) {
        int b = (m0 + w * 32 + mt * 16) >> 4;
        float* dst = g_ninL1 + ((size_t)mp * BB + b) * DE + D;
        #pragma unroll
        for (int nt = 0; nt < 4; nt++) {
            float s0 = fmaxf(acc[mt][nt][0], 0.f) + fmaxf(acc[mt][nt][2], 0.f);
            float s1 = fmaxf(acc[mt][nt][1], 0.f) + fmaxf(acc[mt][nt][3], 0.f);
            #pragma unroll
            for (int o = 4; o < 32; o <<= 1) {
                s0 += __shfl_xor_sync(0xffffffffu, s0, o);
                s1 += __shfl_xor_sync(0xffffffffu, s1, o);
            }
            if (lane < 4) {
                int c = nt * 8 + 2 * lane;
                *(float2*)(dst + c) = make_float2(s0 * inv16, s1 * inv16);
            }
        }
    }
}

// ---------------- final fuse ----------------
__device__ __forceinline__ float blk_red(float v, float* sh) {
    #pragma unroll
    for (int o = 16; o; o >>= 1) v += __shfl_xor_sync(0xffffffffu, v, o);
    int lane = threadIdx.x & 31, wid = threadIdx.x >> 5;
    if (lane == 0) sh[wid] = v;
    __syncthreads();
    float r = sh[0] + sh[1] + sh[2] + sh[3];
    __syncthreads();
    return r;
}

__global__ __launch_bounds__(128) void k_fuse(const float* __restrict__ attn,
                                              const float* __restrict__ fc_w,
                                              const float* __restrict__ fc_b,
                                              float* __restrict__ out) {
    __shared__ float sh[4];
    int b = blockIdx.x, d = threadIdx.x;
    float v0 = g_outs[((size_t)0 * BB + b) * D + d];
    float v1 = g_outs[((size_t)1 * BB + b) * D + d];
    float v2 = g_outs[((size_t)2 * BB + b) * D + d];
    float a  = attn[d];
    float s0 = blk_red(v0 * a, sh);
    float s1 = blk_red(v1 * a, sh);
    float s2 = blk_red(v2 * a, sh);
    s0 = tanhf(s0); s1 = tanhf(s1); s2 = tanhf(s2);
    float mx = fmaxf(s0, fmaxf(s1, s2));
    float e0 = expf(s0 - mx), e1 = expf(s1 - mx), e2 = expf(s2 - mx);
    float inv = 1.f / (e0 + e1 + e2);
    float emb = (e0 * v0 + e1 * v1 + e2 * v2) * inv;
    float n2  = blk_red(emb * emb, sh);
    float nrm = sqrtf(n2);
    emb = emb / fmaxf(nrm, 1e-12f);
    #pragma unroll
    for (int nc = 0; nc < NC; nc++) {
        float r = blk_red(emb * fc_w[d * NC + nc], sh);
        if (d == 0) out[b * NC + nc] = r + fc_b[nc];
    }
}

// ---------------- launch ----------------
extern "C" void kernel_launch(void* const* d_in, const int* in_sizes, int n_in,
                              void* d_out, int out_size) {
    (void)in_sizes; (void)n_in; (void)out_size;
    const int*   ids       = (const int*)  d_in[0];
    const float* feats     = (const float*)d_in[1];
    const float* edge_emb  = (const float*)d_in[2];
    const int*   adj_nodes = (const int*)  d_in[3];
    const int*   adj_edges = (const int*)  d_in[4];
    const float* W_self    = (const float*)d_in[5];
    const float* W_neigh   = (const float*)d_in[6];
    const float* W_edge    = (const float*)d_in[7];
    const float* attn      = (const float*)d_in[8];
    const float* fc_w      = (const float*)d_in[9];
    const float* fc_b      = (const float*)d_in[10];
    float* out = (float*)d_out;

    k_round_w<<<(NMP*2*288*128 + 255) / 256, 256>>>(W_self, W_neigh, W_edge);
    k_idx<<<(NMP * M1 + 255) / 256, 256>>>(ids, adj_nodes, adj_edges);
    k_mean_hop2<<<NMP * M1 / 8, 256>>>(feats, edge_emb, adj_nodes, adj_edges);
    k_mean_hop1<<<NMP * BB / 8, 256>>>(feats, edge_emb);
    gemm_h<0><<<dim3(M1 / 64, NMP), 128>>>(feats, ids, 0);
    gemm_h<1><<<dim3(BB / 64, NMP), 128>>>(feats, ids, 0);
    gemm_edge<<<dim3(M1 / 128, NMP), 128>>>(edge_emb, 0);
    gemm_h<2><<<dim3(BB / 64, NMP), 128>>>(feats, ids, 1);
    k_fuse<<<BB, 128>>>(attn, fc_w, fc_b, out);
}

// round 6
// speedup vs baseline: 1.3882x; 1.3882x over previous
#include <cuda_runtime.h>
#include <cstdint>

#define NMP     3
#define NNODES  50000
#define D       128
#define E       32
#define DEG     32
#define NEDGE   200000
#define BB      1024
#define S       16
#define NC      8
#define M1      (BB*S)      /* 16384 */
#define DE      (D+E)       /* 160 */

#define NSTG    18          /* 288 / 16 k-stages */
#define ASLAB   2560        /* 128 rows * 20 floats (16 data + 4 pad) */
#define BSLAB   2176        /* 16 k * 136 floats (128 data + 8 pad)   */

// ---------------- scratch (static device globals; no runtime alloc) ----------------
__device__ int   g_nb1 [NMP*M1];
__device__ int   g_eid1[NMP*M1];
__device__ float g_nin1[NMP*BB*DE];
__device__ float g_h1  [(size_t)NMP*M1*D];
__device__ float g_h0  [NMP*BB*D];
__device__ float g_ninL1[NMP*BB*DE];
__device__ float g_outs[NMP*BB*D];
// tile-packed A for gemm_h0: [NMP*128 blocks][18 stages][128 rows][20 floats]
__device__ float g_a1pk[(size_t)NMP*128*NSTG*ASLAB];
// tile-packed pre-rounded weights: [NMP*2][18 stages][16][136]
__device__ float g_Whpk[NMP*2*NSTG*BSLAB];

// ---------------- helpers ----------------
__device__ __forceinline__ float tf32r(float x) {
    uint32_t u; asm("cvt.rna.tf32.f32 %0, %1;" : "=r"(u) : "f"(x));
    return __uint_as_float(u);
}
__device__ __forceinline__ uint32_t fu(float x) { return __float_as_uint(x); }
__device__ __forceinline__ uint32_t sptr(const void* p) {
    return (uint32_t)__cvta_generic_to_shared(p);
}
__device__ __forceinline__ void ldsm_x4(uint32_t& d0, uint32_t& d1, uint32_t& d2, uint32_t& d3,
                                        uint32_t a) {
    asm volatile("ldmatrix.sync.aligned.m8n8.x4.shared.b16 {%0,%1,%2,%3}, [%4];"
        : "=r"(d0), "=r"(d1), "=r"(d2), "=r"(d3) : "r"(a));
}
__device__ __forceinline__ uint32_t cvt_frag(uint32_t v) {
    return fu(tf32r(__uint_as_float(v)));
}

#define MMA_TF32(c, a, b) \
    asm volatile("mma.sync.aligned.m16n8k8.row.col.f32.tf32.tf32.f32 " \
        "{%0,%1,%2,%3}, {%4,%5,%6,%7}, {%8,%9}, {%0,%1,%2,%3};" \
        : "+f"((c)[0]), "+f"((c)[1]), "+f"((c)[2]), "+f"((c)[3]) \
        : "r"((a)[0]), "r"((a)[1]), "r"((a)[2]), "r"((a)[3]), \
          "r"((b)[0]), "r"((b)[1]))

#define MBAR_INIT(addr, cnt) \
    asm volatile("mbarrier.init.shared.b64 [%0], %1;" :: "r"(addr), "r"(cnt) : "memory")
#define MBAR_EXPECT_TX(addr, bytes) \
    asm volatile("mbarrier.arrive.expect_tx.shared.b64 _, [%0], %1;" :: "r"(addr), "r"(bytes) : "memory")
#define MBAR_ARRIVE(addr) \
    asm volatile("mbarrier.arrive.shared.b64 _, [%0];" :: "r"(addr) : "memory")
#define MBAR_WAIT(addr, parity) do {                                            \
    uint32_t _m = (addr); uint32_t _p = (parity); uint32_t _done;               \
    asm volatile("{\n\t.reg .pred p;\n\t"                                       \
        "mbarrier.try_wait.parity.acquire.cta.shared::cta.b64 p, [%1], %2;\n\t" \
        "selp.b32 %0, 1, 0, p;\n\t}"                                            \
        : "=r"(_done) : "r"(_m), "r"(_p) : "memory");                           \
    if (!_done) {                                                               \
        asm volatile("{\n\t.reg .pred P1;\n\t"                                  \
            "WL_%=:\n\t"                                                        \
            "mbarrier.try_wait.parity.acquire.cta.shared::cta.b64 P1, [%0], %1, 0x989680;\n\t" \
            "@P1 bra.uni WD_%=;\n\t"                                            \
            "bra.uni WL_%=;\n\t"                                                \
            "WD_%=:\n\t}"                                                       \
            :: "r"(_m), "r"(_p) : "memory");                                    \
    }                                                                           \
} while (0)
#define BULK_CP(dst, src, bytes, mbar) \
    asm volatile("cp.async.bulk.shared::cta.global.mbarrier::complete_tx::bytes [%0], [%1], %2, [%3];" \
        :: "r"(dst), "l"(src), "r"(bytes), "r"(mbar) : "memory")

#define CP16(d, s)  asm volatile("cp.async.cg.shared.global [%0], [%1], 16;" :: "r"(d), "l"(s))
#define CP_COMMIT   asm volatile("cp.async.commit_group;" ::)
#define CP_WAIT(n)  asm volatile("cp.async.wait_group %0;" :: "n"(n))

// ---------------- 0) pack + pre-round weights ----------------
__global__ void k_round_w(const float* __restrict__ W_self,
                          const float* __restrict__ W_neigh) {
    int t = blockIdx.x * blockDim.x + threadIdx.x;
    if (t >= NMP*2*288*128) return;
    int wl = t / (288*128);
    int r  = t % (288*128);
    int k  = r / 128, n = r % 128;
    float v = (k < 128) ? W_self [wl*128*128 + k*128 + n]
                        : W_neigh[wl*160*128 + (k-128)*128 + n];
    int s = k >> 4, kr = k & 15;
    g_Whpk[(size_t)(wl*NSTG + s)*BSLAB + kr*136 + n] = tf32r(v);
}

// ---------------- 1) hop-1 neighbor / edge ids ----------------
__global__ void k_idx(const int* __restrict__ ids,
                      const int* __restrict__ adj_nodes,
                      const int* __restrict__ adj_edges) {
    int t = blockIdx.x * blockDim.x + threadIdx.x;
    if (t >= NMP * M1) return;
    int mp = t / M1;
    int r  = t % M1;
    int b  = r >> 4;
    int s  = r & 15;
    long base = ((long)mp * NNODES + ids[b]) * DEG + s;
    g_nb1[t]  = adj_nodes[base];
    g_eid1[t] = adj_edges[base];
}

// ---------------- 2) hop-2 gather + mean + A-pack ----------------
// warp per row m: packs [feats[nb1[m]] || mean16([feats[nb2]||ee2])] into g_a1pk
__global__ void k_mean_hop2(const float* __restrict__ feats,
                            const float* __restrict__ edge_emb,
                            const int* __restrict__ adj_nodes,
                            const int* __restrict__ adj_edges) {
    int w    = (blockIdx.x * blockDim.x + threadIdx.x) >> 5;
    int lane = threadIdx.x & 31;
    if (w >= NMP * M1) return;
    int mp = w / M1;
    int m  = w % M1;
    int nb1 = g_nb1[w];
    long abase = ((long)mp * NNODES + nb1) * DEG;
    const int* an = adj_nodes + abase;
    const int* ae = adj_edges + abase;
    float4 aF = make_float4(0.f,0.f,0.f,0.f);
    float4 aE = make_float4(0.f,0.f,0.f,0.f);
    #pragma unroll
    for (int s = 0; s < S; s++) {
        int nb = an[s];
        float4 v = ((const float4*)(feats + (long)nb * D))[lane];
        aF.x += v.x; aF.y += v.y; aF.z += v.z; aF.w += v.w;
        if (lane < E/4) {
            int e = ae[s];
            float4 u = ((const float4*)(edge_emb + ((long)mp * NEDGE + e) * E))[lane];
            aE.x += u.x; aE.y += u.y; aE.z += u.z; aE.w += u.w;
        }
    }
    const float inv = 1.0f / S;
    // packed destinations
    int blk = m >> 7, r = m & 127;
    size_t pb = (size_t)(mp * 128 + blk) * NSTG;
    int sq = lane >> 2, o = (lane & 3) * 4;
    // feats[nb1] copy -> stages 0..7
    float4 fv = ((const float4*)(feats + (size_t)nb1 * D))[lane];
    *(float4*)&g_a1pk[(pb + sq) * ASLAB + r * 20 + o] = fv;
    // meanF -> stages 8..15
    *(float4*)&g_a1pk[(pb + 8 + sq) * ASLAB + r * 20 + o] =
        make_float4(aF.x*inv, aF.y*inv, aF.z*inv, aF.w*inv);
    // meanE -> stages 16..17 (lanes 0..7)
    if (lane < E/4)
        *(float4*)&g_a1pk[(pb + 16 + sq) * ASLAB + r * 20 + o] =
            make_float4(aE.x*inv, aE.y*inv, aE.z*inv, aE.w*inv);
}

// ---------------- 3) hop-1 gather + mean -> nin1 ----------------
__global__ void k_mean_hop1(const float* __restrict__ feats,
                            const float* __restrict__ edge_emb) {
    int w    = (blockIdx.x * blockDim.x + threadIdx.x) >> 5;
    int lane = threadIdx.x & 31;
    if (w >= NMP * BB) return;
    int mp = w / BB;
    int b  = w % BB;
    int base = mp * M1 + b * S;
    float4 aF = make_float4(0.f,0.f,0.f,0.f);
    float4 aE = make_float4(0.f,0.f,0.f,0.f);
    #pragma unroll
    for (int s = 0; s < S; s++) {
        int nb = g_nb1[base + s];
        float4 v = ((const float4*)(feats + (long)nb * D))[lane];
        aF.x += v.x; aF.y += v.y; aF.z += v.z; aF.w += v.w;
        if (lane < E/4) {
            int e = g_eid1[base + s];
            float4 u = ((const float4*)(edge_emb + ((long)mp * NEDGE + e) * E))[lane];
            aE.x += u.x; aE.y += u.y; aE.z += u.z; aE.w += u.w;
        }
    }
    const float inv = 1.0f / S;
    float4* o = (float4*)(g_nin1 + (size_t)w * DE);
    o[lane] = make_float4(aF.x*inv, aF.y*inv, aF.z*inv, aF.w*inv);
    if (lane < E/4)
        o[D/4 + lane] = make_float4(aE.x*inv, aE.y*inv, aE.z*inv, aE.w*inv);
}

// ---------------- gemm_h0: bulk-DMA staged TF32 GEMM (M=16384, l=0) ----------------
// h1 = relu(A_packed @ Wh_packed); fused 16-row mean -> g_ninL1[:, :D]
__global__ __launch_bounds__(256) void gemm_h0() {
    constexpr int NS = 3;
    constexpr uint32_t STG_BYTES = (ASLAB + BSLAB) * 4;  // 18944
    extern __shared__ float dsm[];
    __shared__ __align__(8) uint64_t mbar[2 * NS];       // [0..NS) full, [NS..2NS) empty

    int mp  = blockIdx.y;
    int blk = blockIdx.x;
    int m0  = blk * 128;
    int tid  = threadIdx.x;
    int lane = tid & 31;
    int w    = tid >> 5;
    int wm   = w >> 2;          // 0..1
    int wn   = w & 3;           // 0..3
    int row16 = lane & 15;
    int sel4  = (lane >> 4) * 4;
    uint32_t lmoff = (uint32_t)((row16 * 20 + sel4) * 4);

    uint32_t full0  = sptr(&mbar[0]);
    uint32_t empty0 = sptr(&mbar[NS]);

    if (tid == 0) {
        #pragma unroll
        for (int s = 0; s < NS; s++) {
            MBAR_INIT(full0  + s * 8, 1);
            MBAR_INIT(empty0 + s * 8, 256);
        }
    }
    __syncthreads();

    const float* Asrc = g_a1pk + (size_t)(mp * 128 + blk) * NSTG * ASLAB;
    const float* Bsrc = g_Whpk + (size_t)(mp * 2 + 0) * NSTG * BSLAB;
    uint32_t smem0 = sptr(dsm);

    // prologue: issue stages 0..NS-2
    if (tid == 0) {
        #pragma unroll
        for (int t = 0; t < NS - 1; t++) {
            uint32_t fb = full0 + t * 8;
            uint32_t sa = smem0 + t * STG_BYTES;
            MBAR_EXPECT_TX(fb, STG_BYTES);
            BULK_CP(sa,             Asrc + (size_t)t * ASLAB, ASLAB * 4, fb);
            BULK_CP(sa + ASLAB * 4, Bsrc + (size_t)t * BSLAB, BSLAB * 4, fb);
        }
    }

    float acc[4][4][4];
    #pragma unroll
    for (int i = 0; i < 4; i++)
        #pragma unroll
        for (int j = 0; j < 4; j++)
            #pragma unroll
            for (int q = 0; q < 4; q++) acc[i][j][q] = 0.f;

    int cslot = 0, cph = 0;
    int pslot = NS - 1, pph = 1;

    for (int s = 0; s < NSTG; s++) {
        if (tid == 0) {
            int t = s + NS - 1;
            if (t < NSTG) {
                MBAR_WAIT(empty0 + pslot * 8, pph);
                uint32_t fb = full0 + pslot * 8;
                uint32_t sa = smem0 + pslot * STG_BYTES;
                MBAR_EXPECT_TX(fb, STG_BYTES);
                BULK_CP(sa,             Asrc + (size_t)t * ASLAB, ASLAB * 4, fb);
                BULK_CP(sa + ASLAB * 4, Bsrc + (size_t)t * BSLAB, BSLAB * 4, fb);
                if (++pslot == NS) { pslot = 0; pph ^= 1; }
            }
        }
        MBAR_WAIT(full0 + cslot * 8, cph);

        float* As = dsm + cslot * (ASLAB + BSLAB);
        float* Bs = As + ASLAB;
        uint32_t as_base = sptr(As);
        #pragma unroll
        for (int kk = 0; kk < 16; kk += 8) {
            uint32_t afr[4][4], bfr[4][2];
            #pragma unroll
            for (int mt = 0; mt < 4; mt++) {
                uint32_t ad = as_base + (uint32_t)(((wm * 64 + mt * 16) * 20 + kk) * 4) + lmoff;
                ldsm_x4(afr[mt][0], afr[mt][1], afr[mt][2], afr[mt][3], ad);
                afr[mt][0] = cvt_frag(afr[mt][0]);
                afr[mt][1] = cvt_frag(afr[mt][1]);
                afr[mt][2] = cvt_frag(afr[mt][2]);
                afr[mt][3] = cvt_frag(afr[mt][3]);
            }
            #pragma unroll
            for (int nt = 0; nt < 4; nt++) {
                int cN = wn * 32 + nt * 8 + (lane >> 2);
                bfr[nt][0] = fu(Bs[(kk     + (lane & 3)) * 136 + cN]);
                bfr[nt][1] = fu(Bs[(kk + 4 + (lane & 3)) * 136 + cN]);
            }
            #pragma unroll
            for (int mt = 0; mt < 4; mt++)
                #pragma unroll
                for (int nt = 0; nt < 4; nt++)
                    MMA_TF32(acc[mt][nt], afr[mt], bfr[nt]);
        }

        MBAR_ARRIVE(empty0 + cslot * 8);
        if (++cslot == NS) { cslot = 0; cph ^= 1; }
    }

    // relu
    #pragma unroll
    for (int mt = 0; mt < 4; mt++)
        #pragma unroll
        for (int nt = 0; nt < 4; nt++)
            #pragma unroll
            for (int q = 0; q < 4; q++)
                acc[mt][nt][q] = fmaxf(acc[mt][nt][q], 0.f);

    size_t ob = ((size_t)mp * M1 + m0) * D;
    #pragma unroll
    for (int mt = 0; mt < 4; mt++) {
        int r = wm * 64 + mt * 16 + (lane >> 2);
        #pragma unroll
        for (int nt = 0; nt < 4; nt++) {
            int c = wn * 32 + nt * 8 + 2 * (lane & 3);
            *(float2*)(g_h1 + ob + (size_t)r       * D + c) = make_float2(acc[mt][nt][0], acc[mt][nt][1]);
            *(float2*)(g_h1 + ob + (size_t)(r + 8) * D + c) = make_float2(acc[mt][nt][2], acc[mt][nt][3]);
        }
    }

    // fused 16-row mean -> g_ninL1[:, 0:D]
    const float inv16 = 1.0f / 16.0f;
    #pragma unroll
    for (int mt = 0; mt < 4; mt++) {
        int b = (m0 + wm * 64 + mt * 16) >> 4;
        float* dst = g_ninL1 + ((size_t)mp * BB + b) * DE;
        #pragma unroll
        for (int nt = 0; nt < 4; nt++) {
            float s0 = acc[mt][nt][0] + acc[mt][nt][2];
            float s1 = acc[mt][nt][1] + acc[mt][nt][3];
            #pragma unroll
            for (int o = 4; o < 32; o <<= 1) {
                s0 += __shfl_xor_sync(0xffffffffu, s0, o);
                s1 += __shfl_xor_sync(0xffffffffu, s1, o);
            }
            if (lane < 4) {
                int c = wn * 32 + nt * 8 + 2 * lane;
                *(float2*)(dst + c) = make_float2(s0 * inv16, s1 * inv16);
            }
        }
    }
}

// ---------------- small node GEMM (R3-proven cp.async/ldmatrix path), M=1024 ----------------
// MODE 1: h0 (l=0, P1=feats[ids], P2=nin1) -> g_h0
// MODE 2: outs (l=1, P1=g_h0, P2=ninL1)   -> g_outs
template<int MODE>
__global__ __launch_bounds__(256) void gemm_h_small(const float* __restrict__ feats,
                                                    const int*   __restrict__ ids,
                                                    const float* __restrict__ W_self,
                                                    const float* __restrict__ W_neigh,
                                                    int l) {
    constexpr int KTOT = D + DE;
    constexpr int NSG  = KTOT / 16;
    int mp = blockIdx.y;
    int m0 = blockIdx.x * 128;

    __shared__ float As[2][128][20];
    __shared__ float Bs[2][16][136];
    __shared__ const float* rowp[128];

    int tid  = threadIdx.x;
    int lane = tid & 31;
    int w    = tid >> 5;
    int wm   = w >> 2;
    int wn   = w & 3;
    int ar   = tid >> 1;
    int kq   = (tid & 1) * 8;
    int bk   = tid >> 4;
    int bn   = (tid & 15) * 8;
    int row16 = lane & 15;
    int sel4  = (lane >> 4) * 4;
    uint32_t lmoff = (uint32_t)((row16 * 20 + sel4) * 4);

    const float* P2 = (MODE == 1) ? g_nin1 : g_ninL1;
    float* Out      = (MODE == 1) ? g_h0   : g_outs;

    if (tid < 128) {
        int m = m0 + tid;
        rowp[tid] = (MODE == 1) ? (feats + (long)ids[m] * D)
                                : (g_h0 + ((long)mp * BB + m) * D);
    }
    __syncthreads();

    const float* Wsp = W_self  + ((long)(mp * 2 + l)) * D  * D;
    const float* Wnp = W_neigh + ((long)(mp * 2 + l)) * DE * D;
    const float* P2p = P2 + ((size_t)mp * BB + m0) * DE;

    float acc[4][4][4];
    #pragma unroll
    for (int i = 0; i < 4; i++)
        #pragma unroll
        for (int j = 0; j < 4; j++)
            #pragma unroll
            for (int q = 0; q < 4; q++) acc[i][j][q] = 0.f;

    float4 ra0, ra1, rb0, rb1;
#define LDG_H(K0) do {                                                          \
    int _k = (K0);                                                              \
    const float* ap = (_k < D) ? rowp[ar] + _k                                  \
                               : P2p + (long)ar * DE + (_k - D);                \
    ra0 = *(const float4*)(ap + kq);                                            \
    ra1 = *(const float4*)(ap + kq + 4);                                        \
    const float* wrow = (_k < D) ? (Wsp + (long)(_k + bk) * D)                  \
                                 : (Wnp + (long)(_k - D + bk) * D);             \
    rb0 = *(const float4*)(wrow + bn);                                          \
    rb1 = *(const float4*)(wrow + bn + 4);                                      \
} while (0)
#define STS_H(BUF) do {                                                         \
    As[BUF][ar][kq+0] = tf32r(ra0.x); As[BUF][ar][kq+1] = tf32r(ra0.y);         \
    As[BUF][ar][kq+2] = tf32r(ra0.z); As[BUF][ar][kq+3] = tf32r(ra0.w);         \
    As[BUF][ar][kq+4] = tf32r(ra1.x); As[BUF][ar][kq+5] = tf32r(ra1.y);         \
    As[BUF][ar][kq+6] = tf32r(ra1.z); As[BUF][ar][kq+7] = tf32r(ra1.w);         \
    Bs[BUF][bk][bn+0] = tf32r(rb0.x); Bs[BUF][bk][bn+1] = tf32r(rb0.y);         \
    Bs[BUF][bk][bn+2] = tf32r(rb0.z); Bs[BUF][bk][bn+3] = tf32r(rb0.w);         \
    Bs[BUF][bk][bn+4] = tf32r(rb1.x); Bs[BUF][bk][bn+5] = tf32r(rb1.y);         \
    Bs[BUF][bk][bn+6] = tf32r(rb1.z); Bs[BUF][bk][bn+7] = tf32r(rb1.w);         \
} while (0)

    LDG_H(0);
    STS_H(0);
    __syncthreads();

    for (int it = 0; it < NSG; ++it) {
        int cur = it & 1;
        if (it + 1 < NSG) LDG_H((it + 1) * 16);

        uint32_t as_base = sptr(&As[cur][0][0]);
        #pragma unroll
        for (int kk = 0; kk < 16; kk += 8) {
            uint32_t afr[4][4], bfr[4][2];
            #pragma unroll
            for (int mt = 0; mt < 4; mt++) {
                uint32_t ad = as_base + (uint32_t)(((wm * 64 + mt * 16) * 20 + kk) * 4) + lmoff;
                ldsm_x4(afr[mt][0], afr[mt][1], afr[mt][2], afr[mt][3], ad);
            }
            #pragma unroll
            for (int nt = 0; nt < 4; nt++) {
                int cN = wn * 32 + nt * 8 + (lane >> 2);
                bfr[nt][0] = fu(Bs[cur][kk     + (lane & 3)][cN]);
                bfr[nt][1] = fu(Bs[cur][kk + 4 + (lane & 3)][cN]);
            }
            #pragma unroll
            for (int mt = 0; mt < 4; mt++)
                #pragma unroll
                for (int nt = 0; nt < 4; nt++)
                    MMA_TF32(acc[mt][nt], afr[mt], bfr[nt]);
        }
        if (it + 1 < NSG) { STS_H(cur ^ 1); __syncthreads(); }
    }
#undef LDG_H
#undef STS_H

    size_t ob = ((size_t)mp * BB + m0) * D;
    #pragma unroll
    for (int mt = 0; mt < 4; mt++) {
        int r = wm * 64 + mt * 16 + (lane >> 2);
        #pragma unroll
        for (int nt = 0; nt < 4; nt++) {
            int c = wn * 32 + nt * 8 + 2 * (lane & 3);
            float2 v0, v1;
            v0.x = fmaxf(acc[mt][nt][0], 0.f); v0.y = fmaxf(acc[mt][nt][1], 0.f);
            v1.x = fmaxf(acc[mt][nt][2], 0.f); v1.y = fmaxf(acc[mt][nt][3], 0.f);
            *(float2*)(Out + ob + (size_t)r       * D + c) = v0;
            *(float2*)(Out + ob + (size_t)(r + 8) * D + c) = v1;
        }
    }
}

// ---------------- edge GEMM (R3-proven): mean(relu([h0||h1||ee1] @ W_edge)) -> ninL1[:, D:] ----------------
__global__ __launch_bounds__(256) void gemm_edge(const float* __restrict__ edge_emb,
                                                 const float* __restrict__ W_edge,
                                                 int l) {
    constexpr int KTOT = 2 * D + E;
    constexpr int NSG  = KTOT / 16;
    int mp = blockIdx.y;
    int m0 = blockIdx.x * 256;

    __shared__ float As[2][256][20];
    __shared__ float Bs[2][16][40];
    __shared__ const float* pH0s[256];
    __shared__ const float* pH1s[256];
    __shared__ const float* pEs[256];

    int tid  = threadIdx.x;
    int lane = tid & 31;
    int w    = tid >> 5;
    int row16 = lane & 15;
    int sel4  = (lane >> 4) * 4;
    uint32_t lmoff = (uint32_t)((row16 * 20 + sel4) * 4);

    {
        int m = m0 + tid;
        pH0s[tid] = g_h0 + ((long)mp * BB + (m >> 4)) * D;
        pH1s[tid] = g_h1 + ((size_t)mp * M1 + m) * D;
        pEs[tid]  = edge_emb + ((long)mp * NEDGE + g_eid1[mp * M1 + m]) * E;
    }
    __syncthreads();

    const float* Wep = W_edge + ((long)(mp * 2 + l)) * KTOT * E;

    float acc[2][4][4];
    #pragma unroll
    for (int i = 0; i < 2; i++)
        #pragma unroll
        for (int j = 0; j < 4; j++)
            #pragma unroll
            for (int q = 0; q < 4; q++) acc[i][j][q] = 0.f;

    float4 ra0, ra1, rb;
#define LDG_E(K0) do {                                                          \
    int _k = (K0);                                                              \
    const float* ap;                                                            \
    if (_k < D)            ap = pH0s[tid] + _k;                                 \
    else if (_k < 2 * D)   ap = pH1s[tid] + (_k - D);                           \
    else                   ap = pEs[tid]  + (_k - 2 * D);                       \
    ra0 = *(const float4*)(ap);                                                 \
    ra1 = *(const float4*)(ap + 4);                                             \
    float4 ra2 = *(const float4*)(ap + 8);                                      \
    float4 ra3 = *(const float4*)(ap + 12);                                     \
    raX = ra2; raY = ra3;                                                       \
    if (tid < 128)                                                              \
        rb = *(const float4*)(Wep + (long)(_k + (tid >> 3)) * E + (tid & 7) * 4);\
} while (0)
    float4 raX, raY;
#define STS_E(BUF) do {                                                         \
    As[BUF][tid][0]  = tf32r(ra0.x); As[BUF][tid][1]  = tf32r(ra0.y);           \
    As[BUF][tid][2]  = tf32r(ra0.z); As[BUF][tid][3]  = tf32r(ra0.w);           \
    As[BUF][tid][4]  = tf32r(ra1.x); As[BUF][tid][5]  = tf32r(ra1.y);           \
    As[BUF][tid][6]  = tf32r(ra1.z); As[BUF][tid][7]  = tf32r(ra1.w);           \
    As[BUF][tid][8]  = tf32r(raX.x); As[BUF][tid][9]  = tf32r(raX.y);           \
    As[BUF][tid][10] = tf32r(raX.z); As[BUF][tid][11] = tf32r(raX.w);           \
    As[BUF][tid][12] = tf32r(raY.x); As[BUF][tid][13] = tf32r(raY.y);           \
    As[BUF][tid][14] = tf32r(raY.z); As[BUF][tid][15] = tf32r(raY.w);           \
    if (tid < 128) {                                                            \
        int _bk = tid >> 3, _bn = (tid & 7) * 4;                                \
        Bs[BUF][_bk][_bn+0] = tf32r(rb.x); Bs[BUF][_bk][_bn+1] = tf32r(rb.y);   \
        Bs[BUF][_bk][_bn+2] = tf32r(rb.z); Bs[BUF][_bk][_bn+3] = tf32r(rb.w);   \
    }                                                                           \
} while (0)

    LDG_E(0);
    STS_E(0);
    __syncthreads();

    for (int it = 0; it < NSG; ++it) {
        int cur = it & 1;
        if (it + 1 < NSG) LDG_E((it + 1) * 16);

        uint32_t as_base = sptr(&As[cur][0][0]);
        #pragma unroll
        for (int kk = 0; kk < 16; kk += 8) {
            uint32_t afr[2][4], bfr[4][2];
            #pragma unroll
            for (int mt = 0; mt < 2; mt++) {
                uint32_t ad = as_base + (uint32_t)(((w * 32 + mt * 16) * 20 + kk) * 4) + lmoff;
                ldsm_x4(afr[mt][0], afr[mt][1], afr[mt][2], afr[mt][3], ad);
            }
            #pragma unroll
            for (int nt = 0; nt < 4; nt++) {
                int cN = nt * 8 + (lane >> 2);
                bfr[nt][0] = fu(Bs[cur][kk     + (lane & 3)][cN]);
                bfr[nt][1] = fu(Bs[cur][kk + 4 + (lane & 3)][cN]);
            }
            #pragma unroll
            for (int mt = 0; mt < 2; mt++)
                #pragma unroll
                for (int nt = 0; nt < 4; nt++)
                    MMA_TF32(acc[mt][nt], afr[mt], bfr[nt]);
        }
        if (it + 1 < NSG) { STS_E(cur ^ 1); __syncthreads(); }
    }
#undef LDG_E
#undef STS_E

    const float inv16 = 1.0f / 16.0f;
    #pragma unroll
    for (int mt = 0; mt < 2; mt++) {
        int b = (m0 + w * 32 + mt * 16) >> 4;
        float* dst = g_ninL1 + ((size_t)mp * BB + b) * DE + D;
        #pragma unroll
        for (int nt = 0; nt < 4; nt++) {
            float s0 = fmaxf(acc[mt][nt][0], 0.f) + fmaxf(acc[mt][nt][2], 0.f);
            float s1 = fmaxf(acc[mt][nt][1], 0.f) + fmaxf(acc[mt][nt][3], 0.f);
            #pragma unroll
            for (int o = 4; o < 32; o <<= 1) {
                s0 += __shfl_xor_sync(0xffffffffu, s0, o);
                s1 += __shfl_xor_sync(0xffffffffu, s1, o);
            }
            if (lane < 4) {
                int c = nt * 8 + 2 * lane;
                *(float2*)(dst + c) = make_float2(s0 * inv16, s1 * inv16);
            }
        }
    }
}

// ---------------- final fuse ----------------
__device__ __forceinline__ float blk_red(float v, float* sh) {
    #pragma unroll
    for (int o = 16; o; o >>= 1) v += __shfl_xor_sync(0xffffffffu, v, o);
    int lane = threadIdx.x & 31, wid = threadIdx.x >> 5;
    if (lane == 0) sh[wid] = v;
    __syncthreads();
    float r = sh[0] + sh[1] + sh[2] + sh[3];
    __syncthreads();
    return r;
}

__global__ __launch_bounds__(128) void k_fuse(const float* __restrict__ attn,
                                              const float* __restrict__ fc_w,
                                              const float* __restrict__ fc_b,
                                              float* __restrict__ out) {
    __shared__ float sh[4];
    int b = blockIdx.x, d = threadIdx.x;
    float v0 = g_outs[((size_t)0 * BB + b) * D + d];
    float v1 = g_outs[((size_t)1 * BB + b) * D + d];
    float v2 = g_outs[((size_t)2 * BB + b) * D + d];
    float a  = attn[d];
    float s0 = blk_red(v0 * a, sh);
    float s1 = blk_red(v1 * a, sh);
    float s2 = blk_red(v2 * a, sh);
    s0 = tanhf(s0); s1 = tanhf(s1); s2 = tanhf(s2);
    float mx = fmaxf(s0, fmaxf(s1, s2));
    float e0 = expf(s0 - mx), e1 = expf(s1 - mx), e2 = expf(s2 - mx);
    float inv = 1.f / (e0 + e1 + e2);
    float emb = (e0 * v0 + e1 * v1 + e2 * v2) * inv;
    float n2  = blk_red(emb * emb, sh);
    float nrm = sqrtf(n2);
    emb = emb / fmaxf(nrm, 1e-12f);
    #pragma unroll
    for (int nc = 0; nc < NC; nc++) {
        float r = blk_red(emb * fc_w[d * NC + nc], sh);
        if (d == 0) out[b * NC + nc] = r + fc_b[nc];
    }
}

// ---------------- launch ----------------
extern "C" void kernel_launch(void* const* d_in, const int* in_sizes, int n_in,
                              void* d_out, int out_size) {
    (void)in_sizes; (void)n_in; (void)out_size;
    const int*   ids       = (const int*)  d_in[0];
    const float* feats     = (const float*)d_in[1];
    const float* edge_emb  = (const float*)d_in[2];
    const int*   adj_nodes = (const int*)  d_in[3];
    const int*   adj_edges = (const int*)  d_in[4];
    const float* W_self    = (const float*)d_in[5];
    const float* W_neigh   = (const float*)d_in[6];
    const float* W_edge    = (const float*)d_in[7];
    const float* attn      = (const float*)d_in[8];
    const float* fc_w      = (const float*)d_in[9];
    const float* fc_b      = (const float*)d_in[10];
    float* out = (float*)d_out;

    const int SMEM_G0 = 3 * (ASLAB + BSLAB) * 4;   // 56832
    static bool attr_done = false;
    if (!attr_done) {
        cudaFuncSetAttribute(gemm_h0, cudaFuncAttributeMaxDynamicSharedMemorySize, SMEM_G0);
        attr_done = true;
    }

    k_round_w<<<(NMP*2*288*128 + 255) / 256, 256>>>(W_self, W_neigh);
    k_idx<<<(NMP * M1 + 255) / 256, 256>>>(ids, adj_nodes, adj_edges);
    k_mean_hop2<<<NMP * M1 / 8, 256>>>(feats, edge_emb, adj_nodes, adj_edges);
    k_mean_hop1<<<NMP * BB / 8, 256>>>(feats, edge_emb);
    gemm_h0<<<dim3(128, NMP), 256, SMEM_G0>>>();
    gemm_h_small<1><<<dim3(BB / 128, NMP), 256>>>(feats, ids, W_self, W_neigh, 0);
    gemm_edge<<<dim3(M1 / 256, NMP), 256>>>(edge_emb, W_edge, 0);
    gemm_h_small<2><<<dim3(BB / 128, NMP), 256>>>(feats, ids, W_self, W_neigh, 1);
    k_fuse<<<BB, 128>>>(attn, fc_w, fc_b, out);
}

// round 7
// speedup vs baseline: 1.6886x; 1.2164x over previous
#include <cuda_runtime.h>
#include <cstdint>

#define NMP     3
#define NNODES  50000
#define D       128
#define E       32
#define DEG     32
#define NEDGE   200000
#define BB      1024
#define S       16
#define NC      8
#define M1      (BB*S)      /* 16384 */
#define DE      (D+E)       /* 160 */

#define NSTG    18          /* 288 / 16 k-stages */
#define ASLAB   2560        /* 128 rows * 20 floats (16 data + 4 pad) */
#define BSLAB   2176        /* 16 k * 136 floats (128 data + 8 pad)   */
#define EBSLAB  640         /* 16 k * 40 floats (32 data + 8 pad)     */

// ---------------- scratch (static device globals; no runtime alloc) ----------------
__device__ int   g_nb1 [NMP*M1];
__device__ int   g_eid1[NMP*M1];
__device__ float g_nin1[NMP*BB*DE];
__device__ float g_h0  [NMP*BB*D];
__device__ float g_ninL1[NMP*BB*DE];
__device__ float g_outs[NMP*BB*D];
// tile-packed A for gemm_h0: [NMP*128 blocks][18 stages][ASLAB]
__device__ float g_a1pk[(size_t)NMP*128*NSTG*ASLAB];
// tile-packed A for gemm_edge: [NMP*128 blocks][10 slabs][ASLAB]
//   slabs 0..7 = h1 (written by gemm_h0 epilogue), 8..9 = ee1 (k_pack_e)
__device__ float g_epk[(size_t)NMP*128*10*ASLAB];
// tile-packed pre-rounded weights
__device__ float g_Whpk[NMP*2*NSTG*BSLAB];
__device__ float g_Wepk[NMP*2*NSTG*EBSLAB];

// ---------------- helpers ----------------
__device__ __forceinline__ float tf32r(float x) {
    uint32_t u; asm("cvt.rna.tf32.f32 %0, %1;" : "=r"(u) : "f"(x));
    return __uint_as_float(u);
}
__device__ __forceinline__ uint32_t fu(float x) { return __float_as_uint(x); }
__device__ __forceinline__ uint32_t sptr(const void* p) {
    return (uint32_t)__cvta_generic_to_shared(p);
}
__device__ __forceinline__ void ldsm_x4(uint32_t& d0, uint32_t& d1, uint32_t& d2, uint32_t& d3,
                                        uint32_t a) {
    asm volatile("ldmatrix.sync.aligned.m8n8.x4.shared.b16 {%0,%1,%2,%3}, [%4];"
        : "=r"(d0), "=r"(d1), "=r"(d2), "=r"(d3) : "r"(a));
}
__device__ __forceinline__ uint32_t cvt_frag(uint32_t v) {
    return fu(tf32r(__uint_as_float(v)));
}

#define MMA_TF32(c, a, b) \
    asm volatile("mma.sync.aligned.m16n8k8.row.col.f32.tf32.tf32.f32 " \
        "{%0,%1,%2,%3}, {%4,%5,%6,%7}, {%8,%9}, {%0,%1,%2,%3};" \
        : "+f"((c)[0]), "+f"((c)[1]), "+f"((c)[2]), "+f"((c)[3]) \
        : "r"((a)[0]), "r"((a)[1]), "r"((a)[2]), "r"((a)[3]), \
          "r"((b)[0]), "r"((b)[1]))

#define MBAR_INIT(addr, cnt) \
    asm volatile("mbarrier.init.shared.b64 [%0], %1;" :: "r"(addr), "r"(cnt) : "memory")
#define MBAR_EXPECT_TX(addr, bytes) \
    asm volatile("mbarrier.arrive.expect_tx.shared.b64 _, [%0], %1;" :: "r"(addr), "r"(bytes) : "memory")
#define MBAR_ARRIVE(addr) \
    asm volatile("mbarrier.arrive.shared.b64 _, [%0];" :: "r"(addr) : "memory")
#define MBAR_WAIT(addr, parity) do {                                            \
    uint32_t _m = (addr); uint32_t _p = (parity); uint32_t _done;               \
    asm volatile("{\n\t.reg .pred p;\n\t"                                       \
        "mbarrier.try_wait.parity.acquire.cta.shared::cta.b64 p, [%1], %2;\n\t" \
        "selp.b32 %0, 1, 0, p;\n\t}"                                            \
        : "=r"(_done) : "r"(_m), "r"(_p) : "memory");                           \
    if (!_done) {                                                               \
        asm volatile("{\n\t.reg .pred P1;\n\t"                                  \
            "WL_%=:\n\t"                                                        \
            "mbarrier.try_wait.parity.acquire.cta.shared::cta.b64 P1, [%0], %1, 0x989680;\n\t" \
            "@P1 bra.uni WD_%=;\n\t"                                            \
            "bra.uni WL_%=;\n\t"                                                \
            "WD_%=:\n\t}"                                                       \
            :: "r"(_m), "r"(_p) : "memory");                                    \
    }                                                                           \
} while (0)
#define BULK_CP(dst, src, bytes, mbar) \
    asm volatile("cp.async.bulk.shared::cta.global.mbarrier::complete_tx::bytes [%0], [%1], %2, [%3];" \
        :: "r"(dst), "l"(src), "r"(bytes), "r"(mbar) : "memory")

// ---------------- 0) pack + pre-round weights ----------------
__global__ void k_round_w(const float* __restrict__ W_self,
                          const float* __restrict__ W_neigh,
                          const float* __restrict__ W_edge) {
    int t = blockIdx.x * blockDim.x + threadIdx.x;
    if (t < NMP*2*288*128) {
        int wl = t / (288*128);
        int r  = t % (288*128);
        int k  = r / 128, n = r % 128;
        float v = (k < 128) ? W_self [wl*128*128 + k*128 + n]
                            : W_neigh[wl*160*128 + (k-128)*128 + n];
        g_Whpk[(size_t)(wl*NSTG + (k>>4))*BSLAB + (k&15)*136 + n] = tf32r(v);
    }
    if (t < NMP*2*288*32) {
        int wl = t / (288*32);
        int r  = t % (288*32);
        int k  = r / 32, n = r % 32;
        g_Wepk[(size_t)(wl*NSTG + (k>>4))*EBSLAB + (k&15)*40 + n] = tf32r(W_edge[t]);
    }
}

// ---------------- 1) hop-1 neighbor / edge ids ----------------
__global__ void k_idx(const int* __restrict__ ids,
                      const int* __restrict__ adj_nodes,
                      const int* __restrict__ adj_edges) {
    int t = blockIdx.x * blockDim.x + threadIdx.x;
    if (t >= NMP * M1) return;
    int mp = t / M1;
    int r  = t % M1;
    int b  = r >> 4;
    int s  = r & 15;
    long base = ((long)mp * NNODES + ids[b]) * DEG + s;
    g_nb1[t]  = adj_nodes[base];
    g_eid1[t] = adj_edges[base];
}

// ---------------- 2) hop-2 gather + mean + A-pack ----------------
__global__ void k_mean_hop2(const float* __restrict__ feats,
                            const float* __restrict__ edge_emb,
                            const int* __restrict__ adj_nodes,
                            const int* __restrict__ adj_edges) {
    int w    = (blockIdx.x * blockDim.x + threadIdx.x) >> 5;
    int lane = threadIdx.x & 31;
    if (w >= NMP * M1) return;
    int mp = w / M1;
    int m  = w % M1;
    int nb1 = g_nb1[w];
    long abase = ((long)mp * NNODES + nb1) * DEG;
    const int* an = adj_nodes + abase;
    const int* ae = adj_edges + abase;
    float4 aF = make_float4(0.f,0.f,0.f,0.f);
    float4 aE = make_float4(0.f,0.f,0.f,0.f);
    #pragma unroll
    for (int s = 0; s < S; s++) {
        int nb = an[s];
        float4 v = ((const float4*)(feats + (long)nb * D))[lane];
        aF.x += v.x; aF.y += v.y; aF.z += v.z; aF.w += v.w;
        if (lane < E/4) {
            int e = ae[s];
            float4 u = ((const float4*)(edge_emb + ((long)mp * NEDGE + e) * E))[lane];
            aE.x += u.x; aE.y += u.y; aE.z += u.z; aE.w += u.w;
        }
    }
    const float inv = 1.0f / S;
    int blk = m >> 7, r = m & 127;
    size_t pb = (size_t)(mp * 128 + blk) * NSTG;
    int sq = lane >> 2, o = (lane & 3) * 4;
    float4 fv = ((const float4*)(feats + (size_t)nb1 * D))[lane];
    *(float4*)&g_a1pk[(pb + sq) * ASLAB + r * 20 + o] = fv;
    *(float4*)&g_a1pk[(pb + 8 + sq) * ASLAB + r * 20 + o] =
        make_float4(aF.x*inv, aF.y*inv, aF.z*inv, aF.w*inv);
    if (lane < E/4)
        *(float4*)&g_a1pk[(pb + 16 + sq) * ASLAB + r * 20 + o] =
            make_float4(aE.x*inv, aE.y*inv, aE.z*inv, aE.w*inv);
}

// ---------------- 3) hop-1 gather + mean -> nin1 ----------------
__global__ void k_mean_hop1(const float* __restrict__ feats,
                            const float* __restrict__ edge_emb) {
    int w    = (blockIdx.x * blockDim.x + threadIdx.x) >> 5;
    int lane = threadIdx.x & 31;
    if (w >= NMP * BB) return;
    int mp = w / BB;
    int b  = w % BB;
    int base = mp * M1 + b * S;
    float4 aF = make_float4(0.f,0.f,0.f,0.f);
    float4 aE = make_float4(0.f,0.f,0.f,0.f);
    #pragma unroll
    for (int s = 0; s < S; s++) {
        int nb = g_nb1[base + s];
        float4 v = ((const float4*)(feats + (long)nb * D))[lane];
        aF.x += v.x; aF.y += v.y; aF.z += v.z; aF.w += v.w;
        if (lane < E/4) {
            int e = g_eid1[base + s];
            float4 u = ((const float4*)(edge_emb + ((long)mp * NEDGE + e) * E))[lane];
            aE.x += u.x; aE.y += u.y; aE.z += u.z; aE.w += u.w;
        }
    }
    const float inv = 1.0f / S;
    float4* o = (float4*)(g_nin1 + (size_t)w * DE);
    o[lane] = make_float4(aF.x*inv, aF.y*inv, aF.z*inv, aF.w*inv);
    if (lane < E/4)
        o[D/4 + lane] = make_float4(aE.x*inv, aE.y*inv, aE.z*inv, aE.w*inv);
}

// ---------------- 3b) pack ee1 gather -> g_epk slabs 8..9 ----------------
__global__ void k_pack_e(const float* __restrict__ edge_emb) {
    int w    = (blockIdx.x * blockDim.x + threadIdx.x) >> 5;
    int lane = threadIdx.x & 31;
    if (w >= NMP * M1) return;
    int mp = w / M1;
    int m  = w % M1;
    int e  = g_eid1[w];
    float v = edge_emb[((size_t)mp * NEDGE + e) * E + lane];
    int blk = m >> 7, r = m & 127;
    g_epk[((size_t)(mp*128 + blk)*10 + 8 + (lane >> 4)) * ASLAB + r*20 + (lane & 15)] = v;
}

// ---------------- gemm_h0: bulk-DMA staged TF32 GEMM (M=16384, l=0) ----------------
// h1 = relu(A_packed @ Wh_packed) -> g_epk slabs 0..7; fused 16-row mean -> g_ninL1[:, :D]
__global__ __launch_bounds__(256) void gemm_h0() {
    constexpr int NS = 3;
    constexpr uint32_t STG_BYTES = (ASLAB + BSLAB) * 4;
    extern __shared__ float dsm[];
    __shared__ __align__(8) uint64_t mbar[2 * NS];

    int mp  = blockIdx.y;
    int blk = blockIdx.x;
    int m0  = blk * 128;
    int tid  = threadIdx.x;
    int lane = tid & 31;
    int w    = tid >> 5;
    int wm   = w >> 2;
    int wn   = w & 3;
    int row16 = lane & 15;
    int sel4  = (lane >> 4) * 4;
    uint32_t lmoff = (uint32_t)((row16 * 20 + sel4) * 4);

    uint32_t full0  = sptr(&mbar[0]);
    uint32_t empty0 = sptr(&mbar[NS]);

    if (tid == 0) {
        #pragma unroll
        for (int s = 0; s < NS; s++) {
            MBAR_INIT(full0  + s * 8, 1);
            MBAR_INIT(empty0 + s * 8, 256);
        }
    }
    __syncthreads();

    const float* Asrc = g_a1pk + (size_t)(mp * 128 + blk) * NSTG * ASLAB;
    const float* Bsrc = g_Whpk + (size_t)(mp * 2 + 0) * NSTG * BSLAB;
    uint32_t smem0 = sptr(dsm);

    if (tid == 0) {
        #pragma unroll
        for (int t = 0; t < NS - 1; t++) {
            uint32_t fb = full0 + t * 8;
            uint32_t sa = smem0 + t * STG_BYTES;
            MBAR_EXPECT_TX(fb, STG_BYTES);
            BULK_CP(sa,             Asrc + (size_t)t * ASLAB, ASLAB * 4, fb);
            BULK_CP(sa + ASLAB * 4, Bsrc + (size_t)t * BSLAB, BSLAB * 4, fb);
        }
    }

    float acc[4][4][4];
    #pragma unroll
    for (int i = 0; i < 4; i++)
        #pragma unroll
        for (int j = 0; j < 4; j++)
            #pragma unroll
            for (int q = 0; q < 4; q++) acc[i][j][q] = 0.f;

    int cslot = 0, cph = 0;
    int pslot = NS - 1, pph = 1;

    for (int s = 0; s < NSTG; s++) {
        if (tid == 0) {
            int t = s + NS - 1;
            if (t < NSTG) {
                MBAR_WAIT(empty0 + pslot * 8, pph);
                uint32_t fb = full0 + pslot * 8;
                uint32_t sa = smem0 + pslot * STG_BYTES;
                MBAR_EXPECT_TX(fb, STG_BYTES);
                BULK_CP(sa,             Asrc + (size_t)t * ASLAB, ASLAB * 4, fb);
                BULK_CP(sa + ASLAB * 4, Bsrc + (size_t)t * BSLAB, BSLAB * 4, fb);
                if (++pslot == NS) { pslot = 0; pph ^= 1; }
            }
        }
        MBAR_WAIT(full0 + cslot * 8, cph);

        float* As = dsm + cslot * (ASLAB + BSLAB);
        float* Bs = As + ASLAB;
        uint32_t as_base = sptr(As);
        #pragma unroll
        for (int kk = 0; kk < 16; kk += 8) {
            uint32_t afr[4][4], bfr[4][2];
            #pragma unroll
            for (int mt = 0; mt < 4; mt++) {
                uint32_t ad = as_base + (uint32_t)(((wm * 64 + mt * 16) * 20 + kk) * 4) + lmoff;
                ldsm_x4(afr[mt][0], afr[mt][1], afr[mt][2], afr[mt][3], ad);
                afr[mt][0] = cvt_frag(afr[mt][0]);
                afr[mt][1] = cvt_frag(afr[mt][1]);
                afr[mt][2] = cvt_frag(afr[mt][2]);
                afr[mt][3] = cvt_frag(afr[mt][3]);
            }
            #pragma unroll
            for (int nt = 0; nt < 4; nt++) {
                int cN = wn * 32 + nt * 8 + (lane >> 2);
                bfr[nt][0] = fu(Bs[(kk     + (lane & 3)) * 136 + cN]);
                bfr[nt][1] = fu(Bs[(kk + 4 + (lane & 3)) * 136 + cN]);
            }
            #pragma unroll
            for (int mt = 0; mt < 4; mt++)
                #pragma unroll
                for (int nt = 0; nt < 4; nt++)
                    MMA_TF32(acc[mt][nt], afr[mt], bfr[nt]);
        }

        MBAR_ARRIVE(empty0 + cslot * 8);
        if (++cslot == NS) { cslot = 0; cph ^= 1; }
    }

    // relu
    #pragma unroll
    for (int mt = 0; mt < 4; mt++)
        #pragma unroll
        for (int nt = 0; nt < 4; nt++)
            #pragma unroll
            for (int q = 0; q < 4; q++)
                acc[mt][nt][q] = fmaxf(acc[mt][nt][q], 0.f);

    // write h1 into edge-packed slabs 0..7
    float* epb = g_epk + (size_t)(mp * 128 + blk) * 10 * ASLAB;
    int q8 = lane >> 2, c4 = lane & 3;
    #pragma unroll
    for (int mt = 0; mt < 4; mt++) {
        int r = wm * 64 + mt * 16 + q8;
        #pragma unroll
        for (int nt = 0; nt < 4; nt++) {
            int slab = wn * 2 + (nt >> 1);
            int ci   = (nt & 1) * 8 + 2 * c4;
            *(float2*)&epb[(size_t)slab * ASLAB + r       * 20 + ci] = make_float2(acc[mt][nt][0], acc[mt][nt][1]);
            *(float2*)&epb[(size_t)slab * ASLAB + (r + 8) * 20 + ci] = make_float2(acc[mt][nt][2], acc[mt][nt][3]);
        }
    }

    // fused 16-row mean -> g_ninL1[:, 0:D]
    const float inv16 = 1.0f / 16.0f;
    #pragma unroll
    for (int mt = 0; mt < 4; mt++) {
        int b = (m0 + wm * 64 + mt * 16) >> 4;
        float* dst = g_ninL1 + ((size_t)mp * BB + b) * DE;
        #pragma unroll
        for (int nt = 0; nt < 4; nt++) {
            float s0 = acc[mt][nt][0] + acc[mt][nt][2];
            float s1 = acc[mt][nt][1] + acc[mt][nt][3];
            #pragma unroll
            for (int o = 4; o < 32; o <<= 1) {
                s0 += __shfl_xor_sync(0xffffffffu, s0, o);
                s1 += __shfl_xor_sync(0xffffffffu, s1, o);
            }
            if (lane < 4) {
                int c = wn * 32 + nt * 8 + 2 * lane;
                *(float2*)(dst + c) = make_float2(s0 * inv16, s1 * inv16);
            }
        }
    }
}

// ---------------- gemm_edge: bulk-DMA staged TF32; mean(relu(.)) -> ninL1[:, D:] ----------------
// 128 rows/CTA, 8 warps x (16m x 32n). K stages: 0..7 h0 (broadcast), 8..15 h1, 16..17 ee1.
__global__ __launch_bounds__(256) void gemm_edge() {
    constexpr int NS   = 3;
    constexpr int SLOT = ASLAB + EBSLAB;   // floats
    __shared__ float ring[NS * SLOT];
    __shared__ float h0t[8 * 128];
    __shared__ __align__(8) uint64_t mbar[2 * NS + 1];

    int mp  = blockIdx.y;
    int blk = blockIdx.x;
    int m0  = blk * 128;
    int tid  = threadIdx.x;
    int lane = tid & 31;
    int w    = tid >> 5;
    int q    = lane >> 2;
    int c4   = lane & 3;
    int row16 = lane & 15;
    int sel4  = (lane >> 4) * 4;
    uint32_t lmoff = (uint32_t)((row16 * 20 + sel4) * 4);

    uint32_t full0  = sptr(&mbar[0]);
    uint32_t empty0 = sptr(&mbar[NS]);
    uint32_t h0bar  = sptr(&mbar[2 * NS]);

    if (tid == 0) {
        #pragma unroll
        for (int s = 0; s < NS; s++) {
            MBAR_INIT(full0  + s * 8, 1);
            MBAR_INIT(empty0 + s * 8, 256);
        }
        MBAR_INIT(h0bar, 1);
    }
    __syncthreads();

    const float* Apk = g_epk  + (size_t)(mp * 128 + blk) * 10 * ASLAB;
    const float* Bpk = g_Wepk + (size_t)(mp * 2 + 0) * NSTG * EBSLAB;
    const float* H0s = g_h0 + ((size_t)mp * BB + (m0 >> 4)) * D;
    uint32_t ring0 = sptr(ring);

#define ISSUE_EDGE(T, SLOTI) do {                                               \
    int _t = (T);                                                               \
    uint32_t fb = full0 + (SLOTI) * 8;                                          \
    uint32_t sa = ring0 + (SLOTI) * SLOT * 4;                                   \
    uint32_t bytes = EBSLAB * 4 + ((_t >= 8) ? ASLAB * 4 : 0);                  \
    MBAR_EXPECT_TX(fb, bytes);                                                  \
    if (_t >= 8)                                                                \
        BULK_CP(sa, Apk + (size_t)(_t - 8) * ASLAB, ASLAB * 4, fb);             \
    BULK_CP(sa + ASLAB * 4, Bpk + (size_t)_t * EBSLAB, EBSLAB * 4, fb);         \
} while (0)

    if (tid == 0) {
        MBAR_EXPECT_TX(h0bar, 8 * 128 * 4);
        BULK_CP(sptr(h0t), H0s, 8 * 128 * 4, h0bar);
        #pragma unroll
        for (int t = 0; t < NS - 1; t++) ISSUE_EDGE(t, t);
    }
    MBAR_WAIT(h0bar, 0);

    float acc[4][4];
    #pragma unroll
    for (int j = 0; j < 4; j++)
        #pragma unroll
        for (int t = 0; t < 4; t++) acc[j][t] = 0.f;

    int cslot = 0, cph = 0;
    int pslot = NS - 1, pph = 1;

    for (int s = 0; s < NSTG; s++) {
        if (tid == 0) {
            int t = s + NS - 1;
            if (t < NSTG) {
                MBAR_WAIT(empty0 + pslot * 8, pph);
                ISSUE_EDGE(t, pslot);
                if (++pslot == NS) { pslot = 0; pph ^= 1; }
            }
        }
        MBAR_WAIT(full0 + cslot * 8, cph);

        float* As = ring + cslot * SLOT;
        float* Bs = As + ASLAB;
        uint32_t as_base = sptr(As);
        #pragma unroll
        for (int kk = 0; kk < 16; kk += 8) {
            uint32_t afr[4], bfr[4][2];
            if (s < 8) {
                int kb = s * 16 + kk;
                uint32_t v0 = fu(tf32r(h0t[w * 128 + kb + c4]));
                uint32_t v1 = fu(tf32r(h0t[w * 128 + kb + c4 + 4]));
                afr[0] = v0; afr[1] = v0; afr[2] = v1; afr[3] = v1;
            } else {
                uint32_t ad = as_base + (uint32_t)(((w * 16) * 20 + kk) * 4) + lmoff;
                ldsm_x4(afr[0], afr[1], afr[2], afr[3], ad);
                afr[0] = cvt_frag(afr[0]);
                afr[1] = cvt_frag(afr[1]);
                afr[2] = cvt_frag(afr[2]);
                afr[3] = cvt_frag(afr[3]);
            }
            #pragma unroll
            for (int nt = 0; nt < 4; nt++) {
                int cN = nt * 8 + q;
                bfr[nt][0] = fu(Bs[(kk     + c4) * 40 + cN]);
                bfr[nt][1] = fu(Bs[(kk + 4 + c4) * 40 + cN]);
            }
            #pragma unroll
            for (int nt = 0; nt < 4; nt++)
                MMA_TF32(acc[nt], afr, bfr[nt]);
        }

        MBAR_ARRIVE(empty0 + cslot * 8);
        if (++cslot == NS) { cslot = 0; cph ^= 1; }
    }
#undef ISSUE_EDGE

    // relu + 16-row mean -> ninL1[:, D:DE]; warp w covers exactly root b = m0/16 + w
    const float inv16 = 1.0f / 16.0f;
    int b = (m0 >> 4) + w;
    float* dst = g_ninL1 + ((size_t)mp * BB + b) * DE + D;
    #pragma unroll
    for (int nt = 0; nt < 4; nt++) {
        float s0 = fmaxf(acc[nt][0], 0.f) + fmaxf(acc[nt][2], 0.f);
        float s1 = fmaxf(acc[nt][1], 0.f) + fmaxf(acc[nt][3], 0.f);
        #pragma unroll
        for (int o = 4; o < 32; o <<= 1) {
            s0 += __shfl_xor_sync(0xffffffffu, s0, o);
            s1 += __shfl_xor_sync(0xffffffffu, s1, o);
        }
        if (lane < 4) {
            int c = nt * 8 + 2 * lane;
            *(float2*)(dst + c) = make_float2(s0 * inv16, s1 * inv16);
        }
    }
}

// ---------------- small node GEMM (R3-proven cp.async/ldmatrix path), M=1024 ----------------
template<int MODE>
__global__ __launch_bounds__(256) void gemm_h_small(const float* __restrict__ feats,
                                                    const int*   __restrict__ ids,
                                                    const float* __restrict__ W_self,
                                                    const float* __restrict__ W_neigh,
                                                    int l) {
    constexpr int KTOT = D + DE;
    constexpr int NSG  = KTOT / 16;
    int mp = blockIdx.y;
    int m0 = blockIdx.x * 128;

    __shared__ float As[2][128][20];
    __shared__ float Bs[2][16][136];
    __shared__ const float* rowp[128];

    int tid  = threadIdx.x;
    int lane = tid & 31;
    int w    = tid >> 5;
    int wm   = w >> 2;
    int wn   = w & 3;
    int ar   = tid >> 1;
    int kq   = (tid & 1) * 8;
    int bk   = tid >> 4;
    int bn   = (tid & 15) * 8;
    int row16 = lane & 15;
    int sel4  = (lane >> 4) * 4;
    uint32_t lmoff = (uint32_t)((row16 * 20 + sel4) * 4);

    const float* P2 = (MODE == 1) ? g_nin1 : g_ninL1;
    float* Out      = (MODE == 1) ? g_h0   : g_outs;

    if (tid < 128) {
        int m = m0 + tid;
        rowp[tid] = (MODE == 1) ? (feats + (long)ids[m] * D)
                                : (g_h0 + ((long)mp * BB + m) * D);
    }
    __syncthreads();

    const float* Wsp = W_self  + ((long)(mp * 2 + l)) * D  * D;
    const float* Wnp = W_neigh + ((long)(mp * 2 + l)) * DE * D;
    const float* P2p = P2 + ((size_t)mp * BB + m0) * DE;

    float acc[4][4][4];
    #pragma unroll
    for (int i = 0; i < 4; i++)
        #pragma unroll
        for (int j = 0; j < 4; j++)
            #pragma unroll
            for (int q = 0; q < 4; q++) acc[i][j][q] = 0.f;

    float4 ra0, ra1, rb0, rb1;
#define LDG_H(K0) do {                                                          \
    int _k = (K0);                                                              \
    const float* ap = (_k < D) ? rowp[ar] + _k                                  \
                               : P2p + (long)ar * DE + (_k - D);                \
    ra0 = *(const float4*)(ap + kq);                                            \
    ra1 = *(const float4*)(ap + kq + 4);                                        \
    const float* wrow = (_k < D) ? (Wsp + (long)(_k + bk) * D)                  \
                                 : (Wnp + (long)(_k - D + bk) * D);             \
    rb0 = *(const float4*)(wrow + bn);                                          \
    rb1 = *(const float4*)(wrow + bn + 4);                                      \
} while (0)
#define STS_H(BUF) do {                                                         \
    As[BUF][ar][kq+0] = tf32r(ra0.x); As[BUF][ar][kq+1] = tf32r(ra0.y);         \
    As[BUF][ar][kq+2] = tf32r(ra0.z); As[BUF][ar][kq+3] = tf32r(ra0.w);         \
    As[BUF][ar][kq+4] = tf32r(ra1.x); As[BUF][ar][kq+5] = tf32r(ra1.y);         \
    As[BUF][ar][kq+6] = tf32r(ra1.z); As[BUF][ar][kq+7] = tf32r(ra1.w);         \
    Bs[BUF][bk][bn+0] = tf32r(rb0.x); Bs[BUF][bk][bn+1] = tf32r(rb0.y);         \
    Bs[BUF][bk][bn+2] = tf32r(rb0.z); Bs[BUF][bk][bn+3] = tf32r(rb0.w);         \
    Bs[BUF][bk][bn+4] = tf32r(rb1.x); Bs[BUF][bk][bn+5] = tf32r(rb1.y);         \
    Bs[BUF][bk][bn+6] = tf32r(rb1.z); Bs[BUF][bk][bn+7] = tf32r(rb1.w);         \
} while (0)

    LDG_H(0);
    STS_H(0);
    __syncthreads();

    for (int it = 0; it < NSG; ++it) {
        int cur = it & 1;
        if (it + 1 < NSG) LDG_H((it + 1) * 16);

        uint32_t as_base = sptr(&As[cur][0][0]);
        #pragma unroll
        for (int kk = 0; kk < 16; kk += 8) {
            uint32_t afr[4][4], bfr[4][2];
            #pragma unroll
            for (int mt = 0; mt < 4; mt++) {
                uint32_t ad = as_base + (uint32_t)(((wm * 64 + mt * 16) * 20 + kk) * 4) + lmoff;
                ldsm_x4(afr[mt][0], afr[mt][1], afr[mt][2], afr[mt][3], ad);
            }
            #pragma unroll
            for (int nt = 0; nt < 4; nt++) {
                int cN = wn * 32 + nt * 8 + (lane >> 2);
                bfr[nt][0] = fu(Bs[cur][kk     + (lane & 3)][cN]);
                bfr[nt][1] = fu(Bs[cur][kk + 4 + (lane & 3)][cN]);
            }
            #pragma unroll
            for (int mt = 0; mt < 4; mt++)
                #pragma unroll
                for (int nt = 0; nt < 4; nt++)
                    MMA_TF32(acc[mt][nt], afr[mt], bfr[nt]);
        }
        if (it + 1 < NSG) { STS_H(cur ^ 1); __syncthreads(); }
    }
#undef LDG_H
#undef STS_H

    size_t ob = ((size_t)mp * BB + m0) * D;
    #pragma unroll
    for (int mt = 0; mt < 4; mt++) {
        int r = wm * 64 + mt * 16 + (lane >> 2);
        #pragma unroll
        for (int nt = 0; nt < 4; nt++) {
            int c = wn * 32 + nt * 8 + 2 * (lane & 3);
            float2 v0, v1;
            v0.x = fmaxf(acc[mt][nt][0], 0.f); v0.y = fmaxf(acc[mt][nt][1], 0.f);
            v1.x = fmaxf(acc[mt][nt][2], 0.f); v1.y = fmaxf(acc[mt][nt][3], 0.f);
            *(float2*)(Out + ob + (size_t)r       * D + c) = v0;
            *(float2*)(Out + ob + (size_t)(r + 8) * D + c) = v1;
        }
    }
}

// ---------------- final fuse ----------------
__device__ __forceinline__ float blk_red(float v, float* sh) {
    #pragma unroll
    for (int o = 16; o; o >>= 1) v += __shfl_xor_sync(0xffffffffu, v, o);
    int lane = threadIdx.x & 31, wid = threadIdx.x >> 5;
    if (lane == 0) sh[wid] = v;
    __syncthreads();
    float r = sh[0] + sh[1] + sh[2] + sh[3];
    __syncthreads();
    return r;
}

__global__ __launch_bounds__(128) void k_fuse(const float* __restrict__ attn,
                                              const float* __restrict__ fc_w,
                                              const float* __restrict__ fc_b,
                                              float* __restrict__ out) {
    __shared__ float sh[4];
    int b = blockIdx.x, d = threadIdx.x;
    float v0 = g_outs[((size_t)0 * BB + b) * D + d];
    float v1 = g_outs[((size_t)1 * BB + b) * D + d];
    float v2 = g_outs[((size_t)2 * BB + b) * D + d];
    float a  = attn[d];
    float s0 = blk_red(v0 * a, sh);
    float s1 = blk_red(v1 * a, sh);
    float s2 = blk_red(v2 * a, sh);
    s0 = tanhf(s0); s1 = tanhf(s1); s2 = tanhf(s2);
    float mx = fmaxf(s0, fmaxf(s1, s2));
    float e0 = expf(s0 - mx), e1 = expf(s1 - mx), e2 = expf(s2 - mx);
    float inv = 1.f / (e0 + e1 + e2);
    float emb = (e0 * v0 + e1 * v1 + e2 * v2) * inv;
    float n2  = blk_red(emb * emb, sh);
    float nrm = sqrtf(n2);
    emb = emb / fmaxf(nrm, 1e-12f);
    #pragma unroll
    for (int nc = 0; nc < NC; nc++) {
        float r = blk_red(emb * fc_w[d * NC + nc], sh);
        if (d == 0) out[b * NC + nc] = r + fc_b[nc];
    }
}

// ---------------- launch ----------------
extern "C" void kernel_launch(void* const* d_in, const int* in_sizes, int n_in,
                              void* d_out, int out_size) {
    (void)in_sizes; (void)n_in; (void)out_size;
    const int*   ids       = (const int*)  d_in[0];
    const float* feats     = (const float*)d_in[1];
    const float* edge_emb  = (const float*)d_in[2];
    const int*   adj_nodes = (const int*)  d_in[3];
    const int*   adj_edges = (const int*)  d_in[4];
    const float* W_self    = (const float*)d_in[5];
    const float* W_neigh   = (const float*)d_in[6];
    const float* W_edge    = (const float*)d_in[7];
    const float* attn      = (const float*)d_in[8];
    const float* fc_w      = (const float*)d_in[9];
    const float* fc_b      = (const float*)d_in[10];
    float* out = (float*)d_out;

    const int SMEM_G0 = 3 * (ASLAB + BSLAB) * 4;
    static cudaStream_t s1 = nullptr;
    static cudaEvent_t  evA = nullptr, evB = nullptr;
    if (!s1) {
        cudaFuncSetAttribute(gemm_h0, cudaFuncAttributeMaxDynamicSharedMemorySize, SMEM_G0);
        cudaStreamCreateWithFlags(&s1, cudaStreamNonBlocking);
        cudaEventCreateWithFlags(&evA, cudaEventDisableTiming);
        cudaEventCreateWithFlags(&evB, cudaEventDisableTiming);
    }

    // default-stream prefix
    k_round_w<<<(NMP*2*288*128 + 255) / 256, 256>>>(W_self, W_neigh, W_edge);
    k_idx<<<(NMP * M1 + 255) / 256, 256>>>(ids, adj_nodes, adj_edges);
    cudaEventRecord(evA, 0);

    // side chain (under hop2): hop1 mean, ee pack, h0 GEMM
    cudaStreamWaitEvent(s1, evA, 0);
    k_mean_hop1<<<NMP * BB / 8, 256, 0, s1>>>(feats, edge_emb);
    k_pack_e<<<NMP * M1 / 8, 256, 0, s1>>>(edge_emb);
    gemm_h_small<1><<<dim3(BB / 128, NMP), 256, 0, s1>>>(feats, ids, W_self, W_neigh, 0);
    cudaEventRecord(evB, s1);

    // main chain
    k_mean_hop2<<<NMP * M1 / 8, 256>>>(feats, edge_emb, adj_nodes, adj_edges);
    gemm_h0<<<dim3(128, NMP), 256, SMEM_G0>>>();
    cudaStreamWaitEvent(0, evB, 0);
    gemm_edge<<<dim3(128, NMP), 256>>>();
    gemm_h_small<2><<<dim3(BB / 128, NMP), 256>>>(feats, ids, W_self, W_neigh, 1);
    k_fuse<<<BB, 128>>>(attn, fc_w, fc_b, out);
}